// round 2
// baseline (speedup 1.0000x reference)
#include <cuda_runtime.h>
#include <cuda_bf16.h>

// Canny edge detection, exact replica of the JAX reference.
// Strip view: (B*H, W) = (8192, 512). Bitmask: 8 u64 words per row.

#define HH 8192
#define WD 512
#define NWORDS 8          // u64 words per row
#define TROWS 640         // hysteresis tile rows: 128 interior + 2*256 halo
#define HPITCH 9          // padded word pitch in shared (bank spread)

__device__ unsigned long long g_strong[HH * NWORDS];
__device__ unsigned long long g_weak[HH * NWORDS];
__device__ unsigned long long g_tmp[HH * NWORDS];

// ---------------------------------------------------------------------------
// Kernel 1: quantize -> Sobel (replicate pad on strip) -> channel argmax ->
//           NMS (zero pad) -> thresholds -> strong/weak bitmasks.
// Tile: 64 wide x 16 tall output, halo 2 for img, halo 1 for mag.
// ---------------------------------------------------------------------------
__global__ __launch_bounds__(256) void k_grad(const float* __restrict__ xin) {
    __shared__ float simg[3][20][68];
    __shared__ float smag[18][66];
    __shared__ float sgx[18][66];
    __shared__ float sgy[18][66];

    const int tid = threadIdx.x;
    const int x0 = blockIdx.x * 64;
    const int Y0 = blockIdx.y * 16;

    // Phase 1: load quantized image tile with replicate clamp at strip edges.
    for (int i = tid; i < 20 * 68; i += 256) {
        int yy = i / 68, xx = i - yy * 68;
        int GY = Y0 - 2 + yy; GY = max(0, min(HH - 1, GY));
        int GX = x0 - 2 + xx; GX = max(0, min(WD - 1, GX));
        int b = GY >> 9, y = GY & 511;
#pragma unroll
        for (int ch = 0; ch < 3; ++ch) {
            float v = xin[(((b * 3 + ch) << 9) + y) * 512 + GX];
            float t = floorf(((v + 1.0f) * 0.5f) * 255.0f);
            simg[ch][yy][xx] = fminf(fmaxf(t, 0.0f), 255.0f);
        }
    }
    __syncthreads();

    // Phase 2: Sobel per channel, select channel with max L1 magnitude
    // (first max on ties), for the 18x66 halo-1 region.
    for (int i = tid; i < 18 * 66; i += 256) {
        int m = i / 66, n = i - m * 66;
        float bm = -1.0f, bgx = 0.0f, bgy = 0.0f;
#pragma unroll
        for (int ch = 0; ch < 3; ++ch) {
            float i00 = simg[ch][m][n],     i01 = simg[ch][m][n + 1],     i02 = simg[ch][m][n + 2];
            float i10 = simg[ch][m + 1][n],                                i12 = simg[ch][m + 1][n + 2];
            float i20 = simg[ch][m + 2][n], i21 = simg[ch][m + 2][n + 1], i22 = simg[ch][m + 2][n + 2];
            float gx = (i02 + 2.0f * i12 + i22) - (i00 + 2.0f * i10 + i20);
            float gy = (i20 + 2.0f * i21 + i22) - (i00 + 2.0f * i01 + i02);
            float mg = fabsf(gx) + fabsf(gy);
            if (mg > bm) { bm = mg; bgx = gx; bgy = gy; }
        }
        smag[m][n] = bm; sgx[m][n] = bgx; sgy[m][n] = bgy;
    }
    __syncthreads();

    // Phase 3: NMS + thresholds, pack bits via ballot.
    const unsigned lane = tid & 31u;
    const float TG22 = 0.4142135623730951f;
    for (int i = tid; i < 16 * 64; i += 256) {
        int py = i >> 6, px = i & 63;
        float mg = smag[py + 1][px + 1];
        float gx = sgx[py + 1][px + 1];
        float gy = sgy[py + 1][px + 1];
        float ax = fabsf(gx), ay = fabsf(gy);
        bool is_h = ay < TG22 * ax;
        bool is_v = ay * TG22 > ax;
        bool same = (gx * gy) >= 0.0f;
        int d1y, d1x;
        if (is_h)      { d1y = 0;  d1x = -1; }
        else if (is_v) { d1y = -1; d1x = 0;  }
        else if (same) { d1y = -1; d1x = -1; }
        else           { d1y = -1; d1x = 1;  }
        int SY = Y0 + py, SX = x0 + px;
        float n1, n2;
        {
            int ny = SY + d1y, nx = SX + d1x;
            n1 = (ny >= 0 && ny < HH && nx >= 0 && nx < WD)
                     ? smag[py + 1 + d1y][px + 1 + d1x] : 0.0f;
        }
        {
            int ny = SY - d1y, nx = SX - d1x;
            n2 = (ny >= 0 && ny < HH && nx >= 0 && nx < WD)
                     ? smag[py + 1 - d1y][px + 1 - d1x] : 0.0f;
        }
        bool keep = (mg > n1) && (mg >= n2);
        bool strong = keep && (mg > 200.0f);
        bool weak   = keep && (mg > 100.0f);
        unsigned bs = __ballot_sync(0xffffffffu, strong);
        unsigned bw = __ballot_sync(0xffffffffu, weak);
        if (lane == 0) {
            int u32idx = SY * (NWORDS * 2) + (x0 >> 5) + (px >> 5);
            ((unsigned*)g_strong)[u32idx] = bs;
            ((unsigned*)g_weak)[u32idx] = bw;
        }
    }
}

// ---------------------------------------------------------------------------
// Kernel 2: hysteresis — exactly (up to) 256 Jacobi dilation steps per launch.
// Each block: 128 interior rows + 256-row halo each side, double-buffered in
// shared memory. Early break when tile converges (identity steps thereafter).
// dir=0: g_strong -> g_tmp ; dir=1: g_tmp -> g_strong.
// ---------------------------------------------------------------------------
__global__ __launch_bounds__(256) void k_hyst(int dir) {
    extern __shared__ unsigned long long sm[];
    unsigned long long* bufA = sm;
    unsigned long long* bufB = sm + TROWS * HPITCH;
    unsigned long long* sw   = sm + 2 * TROWS * HPITCH;

    const unsigned long long* __restrict__ src = dir ? g_tmp : g_strong;
    unsigned long long* __restrict__ dst = dir ? g_strong : g_tmp;

    const int tid = threadIdx.x;
    const int base = blockIdx.x * 128;

    // Load strip tile (zeros outside strip).
    for (int i = tid; i < TROWS * 8; i += 256) {
        int r = i >> 3, c = i & 7;
        int gr = base - 256 + r;
        unsigned long long s = 0ull, w = 0ull;
        if (gr >= 0 && gr < HH) {
            s = src[gr * 8 + c];
            w = g_weak[gr * 8 + c];
        }
        bufA[r * HPITCH + c] = s;
        sw[r * HPITCH + c] = w;
    }
    __syncthreads();

    unsigned long long* cur = bufA;
    unsigned long long* nxt = bufB;
    const int c = tid & 7;
    const int r0 = (tid >> 3) * 20;

    for (int it = 0; it < 256; ++it) {
        auto hload = [&](int r, unsigned long long& h, unsigned long long& w) {
            if ((unsigned)r >= (unsigned)TROWS) { h = 0ull; w = 0ull; return; }
            unsigned long long ww = cur[r * HPITCH + c];
            unsigned long long wl = (c > 0) ? cur[r * HPITCH + c - 1] : 0ull;
            unsigned long long wr = (c < 7) ? cur[r * HPITCH + c + 1] : 0ull;
            w = ww;
            h = ww | (ww << 1) | (ww >> 1) | (wl >> 63) | (wr << 63);
        };
        unsigned long long Hm, H0, Hp, w0, wp, wd;
        hload(r0 - 1, Hm, wd);
        hload(r0, H0, w0);
        bool changed = false;
#pragma unroll 4
        for (int k = 0; k < 20; ++k) {
            int r = r0 + k;
            hload(r + 1, Hp, wp);
            unsigned long long nw = ((Hm | H0 | Hp) & sw[r * HPITCH + c]) | w0;
            nxt[r * HPITCH + c] = nw;
            changed |= (nw != w0);
            Hm = H0; H0 = Hp; w0 = wp;
        }
        int any = __syncthreads_or(changed ? 1 : 0);
        unsigned long long* t = cur; cur = nxt; nxt = t;
        if (!any) break;
    }

    // Write back interior rows [base, base+128).
    for (int i = tid; i < 128 * 8; i += 256) {
        int rr = i >> 3, cc = i & 7;
        dst[(base + rr) * 8 + cc] = cur[(256 + rr) * HPITCH + cc];
    }
}

// ---------------------------------------------------------------------------
// Kernel 3: bitmask -> (B,3,H,W) float output, values {-1, +1}.
// ---------------------------------------------------------------------------
__global__ __launch_bounds__(256) void k_out(float* __restrict__ out) {
    int idx = blockIdx.x * 256 + threadIdx.x;      // 0 .. 1048575
    int p0 = idx << 2;
    int Y = p0 >> 9;
    int X = p0 & 511;
    unsigned long long w = g_strong[Y * 8 + (X >> 6)];
    int sh = X & 63;
    float4 v;
    v.x = ((w >> sh) & 1ull) ? 1.0f : -1.0f;
    v.y = ((w >> (sh + 1)) & 1ull) ? 1.0f : -1.0f;
    v.z = ((w >> (sh + 2)) & 1ull) ? 1.0f : -1.0f;
    v.w = ((w >> (sh + 3)) & 1ull) ? 1.0f : -1.0f;
    int b = Y >> 9, y = Y & 511;
#pragma unroll
    for (int ch = 0; ch < 3; ++ch) {
        *(float4*)&out[(((b * 3 + ch) << 9) + y) * 512 + X] = v;
    }
}

extern "C" void kernel_launch(void* const* d_in, const int* in_sizes, int n_in,
                              void* d_out, int out_size) {
    const float* x = (const float*)d_in[0];
    float* out = (float*)d_out;

    const int hyst_smem = 3 * TROWS * HPITCH * 8;   // 138,240 bytes
    cudaFuncSetAttribute(k_hyst, cudaFuncAttributeMaxDynamicSharedMemorySize,
                         hyst_smem);

    dim3 g1(WD / 64, HH / 16);                      // (8, 512)
    k_grad<<<g1, 256>>>(x);
    k_hyst<<<HH / 128, 256, hyst_smem>>>(0);        // steps 1..256 (exact)
    k_hyst<<<HH / 128, 256, hyst_smem>>>(1);        // steps 257..512 (exact)
    k_out<<<(HH * WD / 4) / 256, 256>>>(out);
}